// round 15
// baseline (speedup 1.0000x reference)
#include <cuda_runtime.h>
#include <cuda_fp16.h>
#include <mma.h>
#include <cstdint>

using namespace nvcuda;

#define BATCH   2
#define SEQ     8192
#define DMODEL  1024
#define NHEADS  16
#define HD      64
#define NBLK    64
#define BS      128

#define QKV_SEG ((size_t)BATCH * NHEADS * SEQ * HD)   // 16M halves per segment

// ---------------------------------------------------------------------------
// Device scratch
// ---------------------------------------------------------------------------
__device__ __half g_xh[(size_t)BATCH * SEQ * DMODEL];      // fp16 x
__device__ __half g_wqkv[(size_t)3 * DMODEL * DMODEL];     // Wq|Wk|Wv concat (N-dim)
__device__ __half g_wo[(size_t)DMODEL * DMODEL];
__device__ __half g_qkvh[3 * QKV_SEG];                     // q|k|v fp16
__device__ __half g_attnh[(size_t)BATCH * SEQ * DMODEL];   // fp16 attn out

// ---------------------------------------------------------------------------
// merged conversion kernel: x -> g_xh, Wq|Wk|Wv -> g_wqkv, Wo -> g_wo
// ---------------------------------------------------------------------------
#define XN4 ((BATCH * SEQ * DMODEL) / 4)          // 4194304
#define WN4 ((DMODEL * DMODEL) / 4)               // 262144
#define TOTAL4 (XN4 + 4 * WN4)

__global__ void convert_all_kernel(const float* __restrict__ x,
                                   const float* __restrict__ Wq,
                                   const float* __restrict__ Wk,
                                   const float* __restrict__ Wv,
                                   const float* __restrict__ Wo)
{
    int i = blockIdx.x * blockDim.x + threadIdx.x;
    for (; i < TOTAL4; i += gridDim.x * blockDim.x) {
        const float* src;
        __half* dst;
        int loc;
        if (i < XN4) {
            src = x; dst = g_xh; loc = i;
        } else if (i < XN4 + 3 * WN4) {
            int j = i - XN4;
            int which = j / WN4;
            loc = j - which * WN4;
            src = (which == 0) ? Wq : (which == 1) ? Wk : Wv;
            dst = g_wqkv + (size_t)which * (DMODEL * DMODEL);
        } else {
            loc = i - XN4 - 3 * WN4;
            src = Wo; dst = g_wo;
        }
        float4 v = *(const float4*)(src + (size_t)loc * 4);
        __half2 lo = __floats2half2_rn(v.x, v.y);
        __half2 hi = __floats2half2_rn(v.z, v.w);
        uint2 o;
        o.x = *(uint32_t*)&lo;
        o.y = *(uint32_t*)&hi;
        *(uint2*)(dst + (size_t)loc * 4) = o;
    }
}

// ---------------------------------------------------------------------------
// cp.async helpers
// ---------------------------------------------------------------------------
__device__ __forceinline__ uint32_t smem_u32(const void* p) {
    uint32_t a;
    asm("{ .reg .u64 t; cvta.to.shared.u64 t, %1; cvt.u32.u64 %0, t; }" : "=r"(a) : "l"(p));
    return a;
}
#define CP_ASYNC16(dst, src) \
    asm volatile("cp.async.cg.shared.global [%0], [%1], 16;" :: "r"(dst), "l"(src))
#define CP_ASYNC16Z(dst, src, sz) \
    asm volatile("cp.async.cg.shared.global [%0], [%1], 16, %2;" :: "r"(dst), "l"(src), "r"(sz))
#define CP_COMMIT() asm volatile("cp.async.commit_group;")
#define CP_WAIT(N)  asm volatile("cp.async.wait_group %0;" :: "n"(N) : "memory")

// ---------------------------------------------------------------------------
// fp16 GEMM (round-13 banked): BM=BN=128, BK=32, 128 threads, warp 64x64,
// 5-stage cp.async, 102.4KB smem, 2 CTAs/SM.
// ---------------------------------------------------------------------------
#define BKH   32
#define LDH   40
#define NST   5
#define NCH   (DMODEL / BKH)                      // 32
#define TILE_HBYTES (128 * LDH * 2)               // 10240
#define STAGE_BYTES (2 * TILE_HBYTES)             // 20480
#define GEMM_SMEM   (NST * STAGE_BYTES)           // 102400

template <int LAYOUT>
__global__ void __launch_bounds__(128, 2)
gemm_h_kernel(const __half* __restrict__ A, const __half* __restrict__ W,
              const float* __restrict__ b0, const float* __restrict__ b1,
              const float* __restrict__ b2, void* __restrict__ Cv)
{
    extern __shared__ __align__(128) char smem[];
    const uint32_t sbase = smem_u32(smem);
    const int tid  = threadIdx.x;
    const int warp = tid >> 5;
    const int wm   = warp & 1;
    const int wn   = warp >> 1;
    const int m0   = blockIdx.y * 128;
    const int n0   = blockIdx.x * 128;

    const __half* Abase = A + (size_t)m0 * DMODEL;
    const __half* Bbase = W + (size_t)n0 * DMODEL;

    wmma::fragment<wmma::accumulator, 16, 16, 16, float> acc[4][4];
#pragma unroll
    for (int i = 0; i < 4; i++)
#pragma unroll
        for (int j = 0; j < 4; j++)
            wmma::fill_fragment(acc[i][j], 0.0f);

    auto load_stage = [&](int c, int s) {
        const int k0 = c * BKH;
        uint32_t sa = sbase + s * STAGE_BYTES;
#pragma unroll
        for (int i = 0; i < 4; i++) {
            int idx = tid + i * 128;
            int r = idx >> 2, ch = (idx & 3) << 3;
            CP_ASYNC16(sa + (r * LDH + ch) * 2,
                       Abase + (size_t)r * DMODEL + k0 + ch);
        }
#pragma unroll
        for (int i = 0; i < 4; i++) {
            int idx = tid + i * 128;
            int r = idx >> 2, ch = (idx & 3) << 3;
            CP_ASYNC16(sa + TILE_HBYTES + (r * LDH + ch) * 2,
                       Bbase + (size_t)r * DMODEL + k0 + ch);
        }
    };

    load_stage(0, 0); CP_COMMIT();
    load_stage(1, 1); CP_COMMIT();
    load_stage(2, 2); CP_COMMIT();
    load_stage(3, 3); CP_COMMIT();

    for (int c = 0; c < NCH; c++) {
        const int s = c % NST;
        CP_WAIT(3);
        __syncthreads();

        if (c + NST - 1 < NCH) load_stage(c + NST - 1, (c + NST - 1) % NST);
        CP_COMMIT();

        const __half* As = (const __half*)(smem + s * STAGE_BYTES);
        const __half* Bs = (const __half*)(smem + s * STAGE_BYTES + TILE_HBYTES);
#pragma unroll
        for (int ks = 0; ks < BKH / 16; ks++) {
            wmma::fragment<wmma::matrix_a, 16, 16, 16, __half, wmma::row_major> af[4];
#pragma unroll
            for (int i = 0; i < 4; i++)
                wmma::load_matrix_sync(af[i], As + (wm * 64 + i * 16) * LDH + ks * 16, LDH);
#pragma unroll
            for (int j = 0; j < 4; j++) {
                wmma::fragment<wmma::matrix_b, 16, 16, 16, __half, wmma::col_major> bf;
                wmma::load_matrix_sync(bf, Bs + (wn * 64 + j * 16) * LDH + ks * 16, LDH);
#pragma unroll
                for (int i = 0; i < 4; i++)
                    wmma::mma_sync(acc[i][j], af[i], bf, acc[i][j]);
            }
        }
    }

    CP_WAIT(0);
    __syncthreads();

    float* stg = (float*)smem;
#pragma unroll
    for (int i = 0; i < 4; i++)
#pragma unroll
        for (int j = 0; j < 4; j++)
            wmma::store_matrix_sync(&stg[(wm * 64 + i * 16) * 132 + wn * 64 + j * 16],
                                    acc[i][j], 132, wmma::mem_row_major);
    __syncthreads();

    const int which = n0 >> 10;
    const float* bp = (LAYOUT == 0) ? b0
                      : (which == 0 ? b0 : (which == 1 ? b1 : b2));
    const int nseg = (LAYOUT == 0) ? n0 : (n0 & 1023);

#pragma unroll
    for (int i = 0; i < 32; i++) {
        int idx = tid + i * 128;
        int r   = idx >> 5;
        int c4  = (idx & 31) << 2;
        float4 v = *(float4*)&stg[r * 132 + c4];
        float4 bv = *(const float4*)&bp[nseg + c4];
        v.x += bv.x; v.y += bv.y; v.z += bv.z; v.w += bv.w;

        if (LAYOUT == 0) {
            float* C = (float*)Cv;
            *(float4*)&C[(size_t)(m0 + r) * DMODEL + n0 + c4] = v;
        } else {
            __half* C = (__half*)Cv;
            int m  = m0 + r;
            int bb = m >> 13;
            int ss = m & (SEQ - 1);
            int nl = nseg + c4;
            int hh = nl >> 6;
            int d0 = nl & 63;
            __half2 lo = __floats2half2_rn(v.x, v.y);
            __half2 hi = __floats2half2_rn(v.z, v.w);
            uint2 o; o.x = *(uint32_t*)&lo; o.y = *(uint32_t*)&hi;
            *(uint2*)&C[(size_t)which * QKV_SEG +
                        (((size_t)bb * NHEADS + hh) * SEQ + ss) * HD + d0] = o;
        }
    }
}

// ---------------------------------------------------------------------------
// Attention v3: 128 threads, 4 warps, warp tile 32 rows x 64 cols.
// Triple-buffered KV (prefetch dist 2), range-clipped exp, syncwarp chain.
// SMEM 109KB: Sc[128][68] f32 | Ph[128][72] h | KV[3]{K+V [64][72]} | rsum
// ---------------------------------------------------------------------------
#define WKB 64
#define NJ  6
#define SCLD 68
#define PLD  72
#define KVLD 72
#define NKV  3
#define KVBUF_BYTES (2 * WKB * KVLD * 2)          // 18432
#define OFF_PH  (128 * SCLD * 4)                  // 34816
#define OFF_KV  (OFF_PH + 128 * PLD * 2)          // 53248
#define OFF_RS  (OFF_KV + NKV * KVBUF_BYTES)      // 108544
#define ATTN_SMEM (OFF_RS + 512)                  // 109056

__global__ void __launch_bounds__(128)
attn_kernel(const __half* __restrict__ Q, const __half* __restrict__ K,
            const __half* __restrict__ V, __half* __restrict__ O)
{
    extern __shared__ __align__(128) char smem[];
    const uint32_t sbase = smem_u32(smem);
    float*  Sc   = (float*)smem;                  // [128][68]
    __half* Ph   = (__half*)(smem + OFF_PH);      // [128][72]
    float*  rsum = (float*)(smem + OFF_RS);       // [128]

    const int tid  = threadIdx.x;
    const int warp = tid >> 5;                    // 0..3, owns rows 32w..32w+31
    const int n    = blockIdx.x & 63;
    const int h    = (blockIdx.x >> 6) & 15;
    const int b    = blockIdx.x >> 10;
    const size_t base = ((size_t)(b * NHEADS + h)) * SEQ * HD;
    const int kbase = (n - 1) * BS;

    auto load_kv = [&](int j) {
        const uint32_t koff = sbase + OFF_KV + (j % NKV) * KVBUF_BYTES;
        const int kblk = kbase + j * WKB;
#pragma unroll
        for (int i = 0; i < 4; i++) {
            int idx = tid + i * 128;              // 512 jobs
            int r = idx >> 3, ch = (idx & 7) << 3;
            int kpos = kblk + r;
            bool ok = (kpos >= 0 && kpos < SEQ);
            uint32_t sz = ok ? 16u : 0u;
            size_t off = ok ? (base + (size_t)kpos * HD + ch) : base;
            CP_ASYNC16Z(koff + (r * KVLD + ch) * 2, K + off, sz);
            CP_ASYNC16Z(koff + WKB * KVLD * 2 + (r * KVLD + ch) * 2, V + off, sz);
        }
    };

    // KV block 0/1 loads first — latency hides behind Q staging
    load_kv(0); CP_COMMIT();
    load_kv(1); CP_COMMIT();

    // ---- Q (half) -> smem -> register fragments ----
    {
        const __half* qb = Q + base + (size_t)(n * BS) * HD;
#pragma unroll
        for (int i = 0; i < 8; i++) {
            int idx = tid + i * 128;              // 1024 jobs
            int r = idx >> 3, ch = (idx & 7) << 3;
            *(uint4*)(Ph + r * PLD + ch) = *(const uint4*)(qb + (size_t)r * HD + ch);
        }
    }
    __syncthreads();

    wmma::fragment<wmma::matrix_a, 16, 16, 16, __half, wmma::row_major> qf[2][4];
#pragma unroll
    for (int rg = 0; rg < 2; rg++)
#pragma unroll
        for (int ks = 0; ks < 4; ks++)
            wmma::load_matrix_sync(qf[rg][ks],
                Ph + (warp * 32 + rg * 16) * PLD + ks * 16, PLD);
    __syncthreads();   // Ph free for P reuse

    // per-thread softmax row = tid (1 thread/row) — inside own warp's stripe
    const int qrow = tid;
    int klo = qrow;
    if (kbase < 0 && -kbase > klo) klo = -kbase;
    int khi = qrow + 256;
    {
        int lim = SEQ - kbase - 1;
        if (lim < khi) khi = lim;
    }
    float lsum = 0.f;

    wmma::fragment<wmma::accumulator, 16, 16, 16, float> of[2][4];
#pragma unroll
    for (int rg = 0; rg < 2; rg++)
#pragma unroll
        for (int dt = 0; dt < 4; dt++)
            wmma::fill_fragment(of[rg][dt], 0.0f);

    for (int j = 0; j < NJ; j++) {
        CP_WAIT(1);          // block j landed (<=1 pending = j+1 / empty)
        __syncthreads();     // orders reuse of buffer (j+2)%3

        if (j + 2 < NJ) load_kv(j + 2);
        CP_COMMIT();         // unconditional — keeps group count exact

        const __half* Kb = (const __half*)(smem + OFF_KV + (j % NKV) * KVBUF_BYTES);
        const __half* Vb = Kb + WKB * KVLD;

        // ---- S_j = Q @ K_j^T : warp computes rows 32w..32w+31 x 64 ----
#pragma unroll
        for (int nt = 0; nt < 4; nt++) {
            wmma::fragment<wmma::accumulator, 16, 16, 16, float> s0, s1;
            wmma::fill_fragment(s0, 0.0f);
            wmma::fill_fragment(s1, 0.0f);
#pragma unroll
            for (int ks = 0; ks < 4; ks++) {
                wmma::fragment<wmma::matrix_b, 16, 16, 16, __half, wmma::col_major> bf;
                wmma::load_matrix_sync(bf, Kb + (nt * 16) * KVLD + ks * 16, KVLD);
                wmma::mma_sync(s0, qf[0][ks], bf, s0);
                wmma::mma_sync(s1, qf[1][ks], bf, s1);
            }
            wmma::store_matrix_sync(&Sc[(warp * 32) * SCLD + nt * 16], s0,
                                    SCLD, wmma::mem_row_major);
            wmma::store_matrix_sync(&Sc[(warp * 32 + 16) * SCLD + nt * 16], s1,
                                    SCLD, wmma::mem_row_major);
        }
        __syncwarp();        // S rows own-warp; exp reads own row

        // ---- exp + mask -> P halves (range-clipped); row sums ----
        {
            float* row = &Sc[qrow * SCLD];
            __half* prow = Ph + qrow * PLD;
            const int vlo = klo - j * WKB;       // valid col range in this block
            const int vhi = khi - j * WKB;
#pragma unroll
            for (int c = 0; c < WKB; c += 4) {
                if (c + 3 < vlo || c > vhi) {
                    uint2 z; z.x = 0u; z.y = 0u;
                    *(uint2*)&prow[c] = z;
                } else {
                    float4 v = *(float4*)&row[c];
                    float p0 = 0.f, p1 = 0.f, p2 = 0.f, p3 = 0.f;
                    if (c + 0 >= vlo && c + 0 <= vhi) p0 = __expf(v.x * 0.125f);
                    if (c + 1 >= vlo && c + 1 <= vhi) p1 = __expf(v.y * 0.125f);
                    if (c + 2 >= vlo && c + 2 <= vhi) p2 = __expf(v.z * 0.125f);
                    if (c + 3 >= vlo && c + 3 <= vhi) p3 = __expf(v.w * 0.125f);
                    lsum += p0 + p1 + p2 + p3;
                    __half2 lo = __floats2half2_rn(p0, p1);
                    __half2 hi = __floats2half2_rn(p2, p3);
                    uint2 o; o.x = *(uint32_t*)&lo; o.y = *(uint32_t*)&hi;
                    *(uint2*)&prow[c] = o;
                }
            }
        }
        __syncwarp();        // P rows own-warp; pf reads own-warp rows

        // ---- O += P_j @ V_j ----
#pragma unroll
        for (int ks = 0; ks < 4; ks++) {
            wmma::fragment<wmma::matrix_a, 16, 16, 16, __half, wmma::row_major> pf0, pf1;
            wmma::load_matrix_sync(pf0, Ph + (warp * 32) * PLD + ks * 16, PLD);
            wmma::load_matrix_sync(pf1, Ph + (warp * 32 + 16) * PLD + ks * 16, PLD);
#pragma unroll
            for (int dt = 0; dt < 4; dt++) {
                wmma::fragment<wmma::matrix_b, 16, 16, 16, __half, wmma::row_major> vf;
                wmma::load_matrix_sync(vf, Vb + (ks * 16) * KVLD + dt * 16, KVLD);
                wmma::mma_sync(of[0][dt], pf0, vf, of[0][dt]);
                wmma::mma_sync(of[1][dt], pf1, vf, of[1][dt]);
            }
        }
    }

    rsum[qrow] = 1.0f / lsum;

#pragma unroll
    for (int rg = 0; rg < 2; rg++)
#pragma unroll
        for (int dt = 0; dt < 4; dt++)
            wmma::store_matrix_sync(&Sc[(warp * 32 + rg * 16) * SCLD + dt * 16],
                                    of[rg][dt], SCLD, wmma::mem_row_major);
    __syncthreads();

#pragma unroll
    for (int i = 0; i < 8; i++) {
        int idx = tid + i * 128;                  // 1024 jobs
        int r = idx >> 3, ch = (idx & 7) << 3;
        float s = rsum[r];
        float4 f0 = *(float4*)&Sc[r * SCLD + ch];
        float4 f1 = *(float4*)&Sc[r * SCLD + ch + 4];
        __half2 a = __floats2half2_rn(f0.x * s, f0.y * s);
        __half2 bb2 = __floats2half2_rn(f0.z * s, f0.w * s);
        __half2 cc = __floats2half2_rn(f1.x * s, f1.y * s);
        __half2 d = __floats2half2_rn(f1.z * s, f1.w * s);
        uint4 o;
        o.x = *(uint32_t*)&a; o.y = *(uint32_t*)&bb2;
        o.z = *(uint32_t*)&cc; o.w = *(uint32_t*)&d;
        *(uint4*)&O[((size_t)b * SEQ + (size_t)n * BS + r) * DMODEL + h * HD + ch] = o;
    }
}

// ---------------------------------------------------------------------------
// Launch
// ---------------------------------------------------------------------------
extern "C" void kernel_launch(void* const* d_in, const int* in_sizes, int n_in,
                              void* d_out, int out_size)
{
    const float* x  = (const float*)d_in[0];
    const float* Wq = (const float*)d_in[1];
    const float* bq = (const float*)d_in[2];
    const float* Wk = (const float*)d_in[3];
    const float* bk = (const float*)d_in[4];
    const float* Wv = (const float*)d_in[5];
    const float* bv = (const float*)d_in[6];
    const float* Wo = (const float*)d_in[7];
    const float* bo = (const float*)d_in[8];
    float* out = (float*)d_out;

    __half *xh, *wqkv, *wo, *ah, *qkv;
    cudaGetSymbolAddress((void**)&xh,   g_xh);
    cudaGetSymbolAddress((void**)&wqkv, g_wqkv);
    cudaGetSymbolAddress((void**)&wo,   g_wo);
    cudaGetSymbolAddress((void**)&ah,   g_attnh);
    cudaGetSymbolAddress((void**)&qkv,  g_qkvh);

    cudaFuncSetAttribute(gemm_h_kernel<0>,
                         cudaFuncAttributeMaxDynamicSharedMemorySize, GEMM_SMEM);
    cudaFuncSetAttribute(gemm_h_kernel<1>,
                         cudaFuncAttributeMaxDynamicSharedMemorySize, GEMM_SMEM);
    cudaFuncSetAttribute(attn_kernel,
                         cudaFuncAttributeMaxDynamicSharedMemorySize, ATTN_SMEM);

    convert_all_kernel<<<2048, 256>>>(x, Wq, Wk, Wv, Wo);

    dim3 qgrid(3 * DMODEL / 128, (BATCH * SEQ) / 128);   // (24,128)
    gemm_h_kernel<1><<<qgrid, 128, GEMM_SMEM>>>(xh, wqkv, bq, bk, bv, qkv);

    attn_kernel<<<BATCH * NHEADS * NBLK, 128, ATTN_SMEM>>>(
        qkv, qkv + QKV_SEG, qkv + 2 * QKV_SEG, ah);

    dim3 ogrid(DMODEL / 128, (BATCH * SEQ) / 128);       // (8,128)
    gemm_h_kernel<0><<<ogrid, 128, GEMM_SMEM>>>(ah, wo, bo, bo, bo, out);
}

// round 16
// speedup vs baseline: 1.0448x; 1.0448x over previous
#include <cuda_runtime.h>
#include <cuda_fp16.h>
#include <mma.h>
#include <cstdint>

using namespace nvcuda;

#define BATCH   2
#define SEQ     8192
#define DMODEL  1024
#define NHEADS  16
#define HD      64
#define NBLK    64
#define BS      128

#define QKV_SEG ((size_t)BATCH * NHEADS * SEQ * HD)   // 16M halves per segment

// ---------------------------------------------------------------------------
// Device scratch
// ---------------------------------------------------------------------------
__device__ __half g_xh[(size_t)BATCH * SEQ * DMODEL];      // fp16 x
__device__ __half g_wqkv[(size_t)3 * DMODEL * DMODEL];     // Wq|Wk|Wv concat (N-dim)
__device__ __half g_wo[(size_t)DMODEL * DMODEL];
__device__ __half g_qkvh[3 * QKV_SEG];                     // q|k|v fp16
__device__ __half g_attnh[(size_t)BATCH * SEQ * DMODEL];   // fp16 attn out

// ---------------------------------------------------------------------------
// merged conversion kernel: x -> g_xh, Wq|Wk|Wv -> g_wqkv, Wo -> g_wo
// ---------------------------------------------------------------------------
#define XN4 ((BATCH * SEQ * DMODEL) / 4)          // 4194304
#define WN4 ((DMODEL * DMODEL) / 4)               // 262144
#define TOTAL4 (XN4 + 4 * WN4)

__global__ void convert_all_kernel(const float* __restrict__ x,
                                   const float* __restrict__ Wq,
                                   const float* __restrict__ Wk,
                                   const float* __restrict__ Wv,
                                   const float* __restrict__ Wo)
{
    int i = blockIdx.x * blockDim.x + threadIdx.x;
    for (; i < TOTAL4; i += gridDim.x * blockDim.x) {
        const float* src;
        __half* dst;
        int loc;
        if (i < XN4) {
            src = x; dst = g_xh; loc = i;
        } else if (i < XN4 + 3 * WN4) {
            int j = i - XN4;
            int which = j / WN4;
            loc = j - which * WN4;
            src = (which == 0) ? Wq : (which == 1) ? Wk : Wv;
            dst = g_wqkv + (size_t)which * (DMODEL * DMODEL);
        } else {
            loc = i - XN4 - 3 * WN4;
            src = Wo; dst = g_wo;
        }
        float4 v = *(const float4*)(src + (size_t)loc * 4);
        __half2 lo = __floats2half2_rn(v.x, v.y);
        __half2 hi = __floats2half2_rn(v.z, v.w);
        uint2 o;
        o.x = *(uint32_t*)&lo;
        o.y = *(uint32_t*)&hi;
        *(uint2*)(dst + (size_t)loc * 4) = o;
    }
}

// ---------------------------------------------------------------------------
// cp.async helpers
// ---------------------------------------------------------------------------
__device__ __forceinline__ uint32_t smem_u32(const void* p) {
    uint32_t a;
    asm("{ .reg .u64 t; cvta.to.shared.u64 t, %1; cvt.u32.u64 %0, t; }" : "=r"(a) : "l"(p));
    return a;
}
#define CP_ASYNC16(dst, src) \
    asm volatile("cp.async.cg.shared.global [%0], [%1], 16;" :: "r"(dst), "l"(src))
#define CP_ASYNC16Z(dst, src, sz) \
    asm volatile("cp.async.cg.shared.global [%0], [%1], 16, %2;" :: "r"(dst), "l"(src), "r"(sz))
#define CP_COMMIT() asm volatile("cp.async.commit_group;")
#define CP_WAIT(N)  asm volatile("cp.async.wait_group %0;" :: "n"(N) : "memory")

// ---------------------------------------------------------------------------
// fp16 GEMM (banked): BM=BN=128, BK=32, 128 threads, warp 64x64,
// 5-stage cp.async, 102.4KB smem, 2 CTAs/SM.
// ---------------------------------------------------------------------------
#define BKH   32
#define LDH   40
#define NST   5
#define NCH   (DMODEL / BKH)                      // 32
#define TILE_HBYTES (128 * LDH * 2)               // 10240
#define STAGE_BYTES (2 * TILE_HBYTES)             // 20480
#define GEMM_SMEM   (NST * STAGE_BYTES)           // 102400

template <int LAYOUT>
__global__ void __launch_bounds__(128, 2)
gemm_h_kernel(const __half* __restrict__ A, const __half* __restrict__ W,
              const float* __restrict__ b0, const float* __restrict__ b1,
              const float* __restrict__ b2, void* __restrict__ Cv)
{
    extern __shared__ __align__(128) char smem[];
    const uint32_t sbase = smem_u32(smem);
    const int tid  = threadIdx.x;
    const int warp = tid >> 5;
    const int wm   = warp & 1;
    const int wn   = warp >> 1;
    const int m0   = blockIdx.y * 128;
    const int n0   = blockIdx.x * 128;

    const __half* Abase = A + (size_t)m0 * DMODEL;
    const __half* Bbase = W + (size_t)n0 * DMODEL;

    wmma::fragment<wmma::accumulator, 16, 16, 16, float> acc[4][4];
#pragma unroll
    for (int i = 0; i < 4; i++)
#pragma unroll
        for (int j = 0; j < 4; j++)
            wmma::fill_fragment(acc[i][j], 0.0f);

    auto load_stage = [&](int c, int s) {
        const int k0 = c * BKH;
        uint32_t sa = sbase + s * STAGE_BYTES;
#pragma unroll
        for (int i = 0; i < 4; i++) {
            int idx = tid + i * 128;
            int r = idx >> 2, ch = (idx & 3) << 3;
            CP_ASYNC16(sa + (r * LDH + ch) * 2,
                       Abase + (size_t)r * DMODEL + k0 + ch);
        }
#pragma unroll
        for (int i = 0; i < 4; i++) {
            int idx = tid + i * 128;
            int r = idx >> 2, ch = (idx & 3) << 3;
            CP_ASYNC16(sa + TILE_HBYTES + (r * LDH + ch) * 2,
                       Bbase + (size_t)r * DMODEL + k0 + ch);
        }
    };

    load_stage(0, 0); CP_COMMIT();
    load_stage(1, 1); CP_COMMIT();
    load_stage(2, 2); CP_COMMIT();
    load_stage(3, 3); CP_COMMIT();

    for (int c = 0; c < NCH; c++) {
        const int s = c % NST;
        CP_WAIT(3);
        __syncthreads();

        if (c + NST - 1 < NCH) load_stage(c + NST - 1, (c + NST - 1) % NST);
        CP_COMMIT();

        const __half* As = (const __half*)(smem + s * STAGE_BYTES);
        const __half* Bs = (const __half*)(smem + s * STAGE_BYTES + TILE_HBYTES);
#pragma unroll
        for (int ks = 0; ks < BKH / 16; ks++) {
            wmma::fragment<wmma::matrix_a, 16, 16, 16, __half, wmma::row_major> af[4];
#pragma unroll
            for (int i = 0; i < 4; i++)
                wmma::load_matrix_sync(af[i], As + (wm * 64 + i * 16) * LDH + ks * 16, LDH);
#pragma unroll
            for (int j = 0; j < 4; j++) {
                wmma::fragment<wmma::matrix_b, 16, 16, 16, __half, wmma::col_major> bf;
                wmma::load_matrix_sync(bf, Bs + (wn * 64 + j * 16) * LDH + ks * 16, LDH);
#pragma unroll
                for (int i = 0; i < 4; i++)
                    wmma::mma_sync(acc[i][j], af[i], bf, acc[i][j]);
            }
        }
    }

    CP_WAIT(0);
    __syncthreads();

    float* stg = (float*)smem;
#pragma unroll
    for (int i = 0; i < 4; i++)
#pragma unroll
        for (int j = 0; j < 4; j++)
            wmma::store_matrix_sync(&stg[(wm * 64 + i * 16) * 132 + wn * 64 + j * 16],
                                    acc[i][j], 132, wmma::mem_row_major);
    __syncthreads();

    const int which = n0 >> 10;
    const float* bp = (LAYOUT == 0) ? b0
                      : (which == 0 ? b0 : (which == 1 ? b1 : b2));
    const int nseg = (LAYOUT == 0) ? n0 : (n0 & 1023);

#pragma unroll
    for (int i = 0; i < 32; i++) {
        int idx = tid + i * 128;
        int r   = idx >> 5;
        int c4  = (idx & 31) << 2;
        float4 v = *(float4*)&stg[r * 132 + c4];
        float4 bv = *(const float4*)&bp[nseg + c4];
        v.x += bv.x; v.y += bv.y; v.z += bv.z; v.w += bv.w;

        if (LAYOUT == 0) {
            float* C = (float*)Cv;
            *(float4*)&C[(size_t)(m0 + r) * DMODEL + n0 + c4] = v;
        } else {
            __half* C = (__half*)Cv;
            int m  = m0 + r;
            int bb = m >> 13;
            int ss = m & (SEQ - 1);
            int nl = nseg + c4;
            int hh = nl >> 6;
            int d0 = nl & 63;
            __half2 lo = __floats2half2_rn(v.x, v.y);
            __half2 hi = __floats2half2_rn(v.z, v.w);
            uint2 o; o.x = *(uint32_t*)&lo; o.y = *(uint32_t*)&hi;
            *(uint2*)&C[(size_t)which * QKV_SEG +
                        (((size_t)bb * NHEADS + hh) * SEQ + ss) * HD + d0] = o;
        }
    }
}

// ---------------------------------------------------------------------------
// Attention (round-14 config: 256 threads, 8 warps, warp tile 16 rows,
// triple-buffered KV prefetch dist 2) + range-clipped exp skip.
// SMEM 109KB: Sc[128][68] f32 | Ph[128][72] h | KV[3]{K+V [64][72]} | rsum
// ---------------------------------------------------------------------------
#define WKB 64
#define NJ  6
#define SCLD 68
#define PLD  72
#define KVLD 72
#define NKV  3
#define KVBUF_BYTES (2 * WKB * KVLD * 2)          // 18432
#define OFF_PH  (128 * SCLD * 4)                  // 34816
#define OFF_KV  (OFF_PH + 128 * PLD * 2)          // 53248
#define OFF_RS  (OFF_KV + NKV * KVBUF_BYTES)      // 108544
#define ATTN_SMEM (OFF_RS + 512)                  // 109056

__global__ void __launch_bounds__(256)
attn_kernel(const __half* __restrict__ Q, const __half* __restrict__ K,
            const __half* __restrict__ V, __half* __restrict__ O)
{
    extern __shared__ __align__(128) char smem[];
    const uint32_t sbase = smem_u32(smem);
    float*  Sc   = (float*)smem;                  // [128][68]
    __half* Ph   = (__half*)(smem + OFF_PH);      // [128][72]
    float*  rsum = (float*)(smem + OFF_RS);       // [128]

    const int tid  = threadIdx.x;
    const int warp = tid >> 5;
    const int n    = blockIdx.x & 63;
    const int h    = (blockIdx.x >> 6) & 15;
    const int b    = blockIdx.x >> 10;
    const size_t base = ((size_t)(b * NHEADS + h)) * SEQ * HD;
    const int kbase = (n - 1) * BS;

    auto load_kv = [&](int j) {
        const uint32_t koff = sbase + OFF_KV + (j % NKV) * KVBUF_BYTES;
        const int kblk = kbase + j * WKB;
#pragma unroll
        for (int i = 0; i < 2; i++) {
            int idx = tid + i * 256;
            int r = idx >> 3, ch = (idx & 7) << 3;
            int kpos = kblk + r;
            bool ok = (kpos >= 0 && kpos < SEQ);
            uint32_t sz = ok ? 16u : 0u;
            size_t off = ok ? (base + (size_t)kpos * HD + ch) : base;
            CP_ASYNC16Z(koff + (r * KVLD + ch) * 2, K + off, sz);
            CP_ASYNC16Z(koff + WKB * KVLD * 2 + (r * KVLD + ch) * 2, V + off, sz);
        }
    };

    // KV block 0/1 loads first — latency hides behind Q staging
    load_kv(0); CP_COMMIT();
    load_kv(1); CP_COMMIT();

    // ---- Q (half) -> smem -> fragments ----
    {
        const __half* qb = Q + base + (size_t)(n * BS) * HD;
#pragma unroll
        for (int i = 0; i < 4; i++) {
            int idx = tid + i * 256;
            int r = idx >> 3, ch = (idx & 7) << 3;
            *(uint4*)(Ph + r * PLD + ch) = *(const uint4*)(qb + (size_t)r * HD + ch);
        }
    }
    __syncthreads();

    wmma::fragment<wmma::matrix_a, 16, 16, 16, __half, wmma::row_major> qf[4];
#pragma unroll
    for (int ks = 0; ks < 4; ks++)
        wmma::load_matrix_sync(qf[ks], Ph + (warp * 16) * PLD + ks * 16, PLD);
    __syncthreads();   // Ph free for P reuse

    const int qrow = tid >> 1;
    const int par  = tid & 1;
    int klo = qrow;
    if (kbase < 0 && -kbase > klo) klo = -kbase;
    int khi = qrow + 256;
    {
        int lim = SEQ - kbase - 1;
        if (lim < khi) khi = lim;
    }
    float lsum = 0.f;

    wmma::fragment<wmma::accumulator, 16, 16, 16, float> of[4];
#pragma unroll
    for (int dt = 0; dt < 4; dt++) wmma::fill_fragment(of[dt], 0.0f);

    for (int j = 0; j < NJ; j++) {
        CP_WAIT(1);          // block j landed (<=1 pending = j+1 / empty)
        __syncthreads();     // orders reuse of buffer (j+2)%3

        if (j + 2 < NJ) load_kv(j + 2);
        CP_COMMIT();         // unconditional — keeps group count exact

        const __half* Kb = (const __half*)(smem + OFF_KV + (j % NKV) * KVBUF_BYTES);
        const __half* Vb = Kb + WKB * KVLD;

        // ---- S_j = Q @ K_j^T ----
#pragma unroll
        for (int nt = 0; nt < 4; nt++) {
            wmma::fragment<wmma::accumulator, 16, 16, 16, float> sacc;
            wmma::fill_fragment(sacc, 0.0f);
#pragma unroll
            for (int ks = 0; ks < 4; ks++) {
                wmma::fragment<wmma::matrix_b, 16, 16, 16, __half, wmma::col_major> bf;
                wmma::load_matrix_sync(bf, Kb + (nt * 16) * KVLD + ks * 16, KVLD);
                wmma::mma_sync(sacc, qf[ks], bf, sacc);
            }
            wmma::store_matrix_sync(&Sc[(warp * 16) * SCLD + nt * 16], sacc,
                                    SCLD, wmma::mem_row_major);
        }
        __syncwarp();

        // ---- exp + mask -> P halves (range-clipped); row sums ----
        {
            float* row = &Sc[qrow * SCLD];
            __half* prow = Ph + qrow * PLD;
            const int c0 = par * 32;
            const int vlo = klo - j * WKB;       // valid col range in this block
            const int vhi = khi - j * WKB;
#pragma unroll
            for (int c4 = 0; c4 < 32; c4 += 4) {
                int c = c0 + c4;
                if (c + 3 < vlo || c > vhi) {
                    uint2 z; z.x = 0u; z.y = 0u;
                    *(uint2*)&prow[c] = z;
                } else {
                    float4 v = *(float4*)&row[c];
                    float p0 = 0.f, p1 = 0.f, p2 = 0.f, p3 = 0.f;
                    if (c + 0 >= vlo && c + 0 <= vhi) p0 = __expf(v.x * 0.125f);
                    if (c + 1 >= vlo && c + 1 <= vhi) p1 = __expf(v.y * 0.125f);
                    if (c + 2 >= vlo && c + 2 <= vhi) p2 = __expf(v.z * 0.125f);
                    if (c + 3 >= vlo && c + 3 <= vhi) p3 = __expf(v.w * 0.125f);
                    lsum += p0 + p1 + p2 + p3;
                    __half2 lo = __floats2half2_rn(p0, p1);
                    __half2 hi = __floats2half2_rn(p2, p3);
                    uint2 o; o.x = *(uint32_t*)&lo; o.y = *(uint32_t*)&hi;
                    *(uint2*)&prow[c] = o;
                }
            }
        }
        __syncwarp();

        // ---- O += P_j @ V_j ----
#pragma unroll
        for (int ks = 0; ks < 4; ks++) {
            wmma::fragment<wmma::matrix_a, 16, 16, 16, __half, wmma::row_major> pf;
            wmma::load_matrix_sync(pf, Ph + (warp * 16) * PLD + ks * 16, PLD);
#pragma unroll
            for (int dt = 0; dt < 4; dt++) {
                wmma::fragment<wmma::matrix_b, 16, 16, 16, __half, wmma::row_major> vf;
                wmma::load_matrix_sync(vf, Vb + (ks * 16) * KVLD + dt * 16, KVLD);
                wmma::mma_sync(of[dt], pf, vf, of[dt]);
            }
        }
    }

    lsum += __shfl_xor_sync(0xFFFFFFFF, lsum, 1);
    if (par == 0) rsum[qrow] = 1.0f / lsum;

#pragma unroll
    for (int dt = 0; dt < 4; dt++)
        wmma::store_matrix_sync(&Sc[(warp * 16) * SCLD + dt * 16], of[dt],
                                SCLD, wmma::mem_row_major);
    __syncthreads();

#pragma unroll
    for (int i = 0; i < 4; i++) {
        int idx = tid + i * 256;
        int r = idx >> 3, ch = (idx & 7) << 3;
        float s = rsum[r];
        float4 f0 = *(float4*)&Sc[r * SCLD + ch];
        float4 f1 = *(float4*)&Sc[r * SCLD + ch + 4];
        __half2 a = __floats2half2_rn(f0.x * s, f0.y * s);
        __half2 bb2 = __floats2half2_rn(f0.z * s, f0.w * s);
        __half2 cc = __floats2half2_rn(f1.x * s, f1.y * s);
        __half2 d = __floats2half2_rn(f1.z * s, f1.w * s);
        uint4 o;
        o.x = *(uint32_t*)&a; o.y = *(uint32_t*)&bb2;
        o.z = *(uint32_t*)&cc; o.w = *(uint32_t*)&d;
        *(uint4*)&O[((size_t)b * SEQ + (size_t)n * BS + r) * DMODEL + h * HD + ch] = o;
    }
}

// ---------------------------------------------------------------------------
// Launch
// ---------------------------------------------------------------------------
extern "C" void kernel_launch(void* const* d_in, const int* in_sizes, int n_in,
                              void* d_out, int out_size)
{
    const float* x  = (const float*)d_in[0];
    const float* Wq = (const float*)d_in[1];
    const float* bq = (const float*)d_in[2];
    const float* Wk = (const float*)d_in[3];
    const float* bk = (const float*)d_in[4];
    const float* Wv = (const float*)d_in[5];
    const float* bv = (const float*)d_in[6];
    const float* Wo = (const float*)d_in[7];
    const float* bo = (const float*)d_in[8];
    float* out = (float*)d_out;

    __half *xh, *wqkv, *wo, *ah, *qkv;
    cudaGetSymbolAddress((void**)&xh,   g_xh);
    cudaGetSymbolAddress((void**)&wqkv, g_wqkv);
    cudaGetSymbolAddress((void**)&wo,   g_wo);
    cudaGetSymbolAddress((void**)&ah,   g_attnh);
    cudaGetSymbolAddress((void**)&qkv,  g_qkvh);

    cudaFuncSetAttribute(gemm_h_kernel<0>,
                         cudaFuncAttributeMaxDynamicSharedMemorySize, GEMM_SMEM);
    cudaFuncSetAttribute(gemm_h_kernel<1>,
                         cudaFuncAttributeMaxDynamicSharedMemorySize, GEMM_SMEM);
    cudaFuncSetAttribute(attn_kernel,
                         cudaFuncAttributeMaxDynamicSharedMemorySize, ATTN_SMEM);

    convert_all_kernel<<<2048, 256>>>(x, Wq, Wk, Wv, Wo);

    dim3 qgrid(3 * DMODEL / 128, (BATCH * SEQ) / 128);   // (24,128)
    gemm_h_kernel<1><<<qgrid, 128, GEMM_SMEM>>>(xh, wqkv, bq, bk, bv, qkv);

    attn_kernel<<<BATCH * NHEADS * NBLK, 256, ATTN_SMEM>>>(
        qkv, qkv + QKV_SEG, qkv + 2 * QKV_SEG, ah);

    dim3 ogrid(DMODEL / 128, (BATCH * SEQ) / 128);       // (8,128)
    gemm_h_kernel<0><<<ogrid, 128, GEMM_SMEM>>>(ah, wo, bo, bo, bo, out);
}

// round 17
// speedup vs baseline: 1.1511x; 1.1018x over previous
#include <cuda_runtime.h>
#include <cuda_fp16.h>
#include <mma.h>
#include <cstdint>

using namespace nvcuda;

#define BATCH   2
#define SEQ     8192
#define DMODEL  1024
#define NHEADS  16
#define HD      64
#define NBLK    64
#define BS      128

#define QKV_SEG ((size_t)BATCH * NHEADS * SEQ * HD)   // 16M halves per segment

// ---------------------------------------------------------------------------
// Device scratch
// ---------------------------------------------------------------------------
__device__ __half g_xh[(size_t)BATCH * SEQ * DMODEL];      // fp16 x
__device__ __half g_wqkv[(size_t)3 * DMODEL * DMODEL];     // Wq|Wk|Wv concat (N-dim)
__device__ __half g_wo[(size_t)DMODEL * DMODEL];
__device__ __half g_qkvh[3 * QKV_SEG];                     // q|k|v fp16
__device__ __half g_attnh[(size_t)BATCH * SEQ * DMODEL];   // fp16 attn out

// ---------------------------------------------------------------------------
// merged conversion kernel
// ---------------------------------------------------------------------------
#define XN4 ((BATCH * SEQ * DMODEL) / 4)
#define WN4 ((DMODEL * DMODEL) / 4)
#define TOTAL4 (XN4 + 4 * WN4)

__global__ void convert_all_kernel(const float* __restrict__ x,
                                   const float* __restrict__ Wq,
                                   const float* __restrict__ Wk,
                                   const float* __restrict__ Wv,
                                   const float* __restrict__ Wo)
{
    int i = blockIdx.x * blockDim.x + threadIdx.x;
    for (; i < TOTAL4; i += gridDim.x * blockDim.x) {
        const float* src;
        __half* dst;
        int loc;
        if (i < XN4) {
            src = x; dst = g_xh; loc = i;
        } else if (i < XN4 + 3 * WN4) {
            int j = i - XN4;
            int which = j / WN4;
            loc = j - which * WN4;
            src = (which == 0) ? Wq : (which == 1) ? Wk : Wv;
            dst = g_wqkv + (size_t)which * (DMODEL * DMODEL);
        } else {
            loc = i - XN4 - 3 * WN4;
            src = Wo; dst = g_wo;
        }
        float4 v = *(const float4*)(src + (size_t)loc * 4);
        __half2 lo = __floats2half2_rn(v.x, v.y);
        __half2 hi = __floats2half2_rn(v.z, v.w);
        uint2 o;
        o.x = *(uint32_t*)&lo;
        o.y = *(uint32_t*)&hi;
        *(uint2*)(dst + (size_t)loc * 4) = o;
    }
}

// ---------------------------------------------------------------------------
// helpers
// ---------------------------------------------------------------------------
__device__ __forceinline__ uint32_t smem_u32(const void* p) {
    uint32_t a;
    asm("{ .reg .u64 t; cvta.to.shared.u64 t, %1; cvt.u32.u64 %0, t; }" : "=r"(a) : "l"(p));
    return a;
}
#define CP_ASYNC16(dst, src) \
    asm volatile("cp.async.cg.shared.global [%0], [%1], 16;" :: "r"(dst), "l"(src))
#define CP_ASYNC16Z(dst, src, sz) \
    asm volatile("cp.async.cg.shared.global [%0], [%1], 16, %2;" :: "r"(dst), "l"(src), "r"(sz))
#define CP_COMMIT() asm volatile("cp.async.commit_group;")
#define CP_WAIT(N)  asm volatile("cp.async.wait_group %0;" :: "n"(N) : "memory")

#define LDM_X4(r0, r1, r2, r3, addr) \
    asm volatile("ldmatrix.sync.aligned.m8n8.x4.shared.b16 {%0,%1,%2,%3}, [%4];" \
        : "=r"(r0), "=r"(r1), "=r"(r2), "=r"(r3) : "r"(addr))
#define LDM_X4T(r0, r1, r2, r3, addr) \
    asm volatile("ldmatrix.sync.aligned.m8n8.x4.trans.shared.b16 {%0,%1,%2,%3}, [%4];" \
        : "=r"(r0), "=r"(r1), "=r"(r2), "=r"(r3) : "r"(addr))

__device__ __forceinline__ void mma16816(float* c, const uint32_t* a, const uint32_t* b) {
    asm volatile("mma.sync.aligned.m16n8k16.row.col.f32.f16.f16.f32 "
        "{%0,%1,%2,%3}, {%4,%5,%6,%7}, {%8,%9}, {%0,%1,%2,%3};"
        : "+f"(c[0]), "+f"(c[1]), "+f"(c[2]), "+f"(c[3])
        : "r"(a[0]), "r"(a[1]), "r"(a[2]), "r"(a[3]), "r"(b[0]), "r"(b[1]));
}
__device__ __forceinline__ uint32_t packh2(float a, float b) {
    __half2 h = __floats2half2_rn(a, b);
    return *(uint32_t*)&h;
}

// ---------------------------------------------------------------------------
// fp16 GEMM (banked): BM=BN=128, BK=32, 128 threads, warp 64x64,
// 5-stage cp.async, 102.4KB smem, 2 CTAs/SM.
// ---------------------------------------------------------------------------
#define BKH   32
#define LDHW  40
#define NST   5
#define NCH   (DMODEL / BKH)
#define TILE_HBYTES (128 * LDHW * 2)
#define STAGE_BYTES (2 * TILE_HBYTES)
#define GEMM_SMEM   (NST * STAGE_BYTES)

template <int LAYOUT>
__global__ void __launch_bounds__(128, 2)
gemm_h_kernel(const __half* __restrict__ A, const __half* __restrict__ W,
              const float* __restrict__ b0, const float* __restrict__ b1,
              const float* __restrict__ b2, void* __restrict__ Cv)
{
    extern __shared__ __align__(128) char smem[];
    const uint32_t sbase = smem_u32(smem);
    const int tid  = threadIdx.x;
    const int warp = tid >> 5;
    const int wm   = warp & 1;
    const int wn   = warp >> 1;
    const int m0   = blockIdx.y * 128;
    const int n0   = blockIdx.x * 128;

    const __half* Abase = A + (size_t)m0 * DMODEL;
    const __half* Bbase = W + (size_t)n0 * DMODEL;

    wmma::fragment<wmma::accumulator, 16, 16, 16, float> acc[4][4];
#pragma unroll
    for (int i = 0; i < 4; i++)
#pragma unroll
        for (int j = 0; j < 4; j++)
            wmma::fill_fragment(acc[i][j], 0.0f);

    auto load_stage = [&](int c, int s) {
        const int k0 = c * BKH;
        uint32_t sa = sbase + s * STAGE_BYTES;
#pragma unroll
        for (int i = 0; i < 4; i++) {
            int idx = tid + i * 128;
            int r = idx >> 2, ch = (idx & 3) << 3;
            CP_ASYNC16(sa + (r * LDHW + ch) * 2,
                       Abase + (size_t)r * DMODEL + k0 + ch);
        }
#pragma unroll
        for (int i = 0; i < 4; i++) {
            int idx = tid + i * 128;
            int r = idx >> 2, ch = (idx & 3) << 3;
            CP_ASYNC16(sa + TILE_HBYTES + (r * LDHW + ch) * 2,
                       Bbase + (size_t)r * DMODEL + k0 + ch);
        }
    };

    load_stage(0, 0); CP_COMMIT();
    load_stage(1, 1); CP_COMMIT();
    load_stage(2, 2); CP_COMMIT();
    load_stage(3, 3); CP_COMMIT();

    for (int c = 0; c < NCH; c++) {
        const int s = c % NST;
        CP_WAIT(3);
        __syncthreads();

        if (c + NST - 1 < NCH) load_stage(c + NST - 1, (c + NST - 1) % NST);
        CP_COMMIT();

        const __half* As = (const __half*)(smem + s * STAGE_BYTES);
        const __half* Bs = (const __half*)(smem + s * STAGE_BYTES + TILE_HBYTES);
#pragma unroll
        for (int ks = 0; ks < BKH / 16; ks++) {
            wmma::fragment<wmma::matrix_a, 16, 16, 16, __half, wmma::row_major> af[4];
#pragma unroll
            for (int i = 0; i < 4; i++)
                wmma::load_matrix_sync(af[i], As + (wm * 64 + i * 16) * LDHW + ks * 16, LDHW);
#pragma unroll
            for (int j = 0; j < 4; j++) {
                wmma::fragment<wmma::matrix_b, 16, 16, 16, __half, wmma::col_major> bf;
                wmma::load_matrix_sync(bf, Bs + (wn * 64 + j * 16) * LDHW + ks * 16, LDHW);
#pragma unroll
                for (int i = 0; i < 4; i++)
                    wmma::mma_sync(acc[i][j], af[i], bf, acc[i][j]);
            }
        }
    }

    CP_WAIT(0);
    __syncthreads();

    float* stg = (float*)smem;
#pragma unroll
    for (int i = 0; i < 4; i++)
#pragma unroll
        for (int j = 0; j < 4; j++)
            wmma::store_matrix_sync(&stg[(wm * 64 + i * 16) * 132 + wn * 64 + j * 16],
                                    acc[i][j], 132, wmma::mem_row_major);
    __syncthreads();

    const int which = n0 >> 10;
    const float* bp = (LAYOUT == 0) ? b0
                      : (which == 0 ? b0 : (which == 1 ? b1 : b2));
    const int nseg = (LAYOUT == 0) ? n0 : (n0 & 1023);

#pragma unroll
    for (int i = 0; i < 32; i++) {
        int idx = tid + i * 128;
        int r   = idx >> 5;
        int c4  = (idx & 31) << 2;
        float4 v = *(float4*)&stg[r * 132 + c4];
        float4 bv = *(const float4*)&bp[nseg + c4];
        v.x += bv.x; v.y += bv.y; v.z += bv.z; v.w += bv.w;

        if (LAYOUT == 0) {
            float* C = (float*)Cv;
            *(float4*)&C[(size_t)(m0 + r) * DMODEL + n0 + c4] = v;
        } else {
            __half* C = (__half*)Cv;
            int m  = m0 + r;
            int bb = m >> 13;
            int ss = m & (SEQ - 1);
            int nl = nseg + c4;
            int hh = nl >> 6;
            int d0 = nl & 63;
            __half2 lo = __floats2half2_rn(v.x, v.y);
            __half2 hi = __floats2half2_rn(v.z, v.w);
            uint2 o; o.x = *(uint32_t*)&lo; o.y = *(uint32_t*)&hi;
            *(uint2*)&C[(size_t)which * QKV_SEG +
                        (((size_t)bb * NHEADS + hh) * SEQ + ss) * HD + d0] = o;
        }
    }
}

// ---------------------------------------------------------------------------
// Attention v4: FA2-style register-resident softmax (mma.m16n8k16 + ldmatrix).
// 256 threads, 8 warps x 16 query rows. Triple-buffered KV cp.async.
// Per iter: S in C-frags -> exp in regs -> P A-frags -> PV. No smem S/P.
// SMEM 90.2KB: [Sc f32 128x68 | alias Ph h 128x72] | KV[3]{K+V [64][72]}
// ---------------------------------------------------------------------------
#define WKB 64
#define NJ  6
#define SCLD 68
#define PLD  72
#define KVLD 72
#define NKV  3
#define KVBUF_BYTES (2 * WKB * KVLD * 2)          // 18432
#define OFF_KV (128 * SCLD * 4)                   // 34816
#define ATTN_SMEM (OFF_KV + NKV * KVBUF_BYTES + 128)   // 90240

__global__ void __launch_bounds__(256, 2)
attn_kernel(const __half* __restrict__ Q, const __half* __restrict__ K,
            const __half* __restrict__ V, __half* __restrict__ O)
{
    extern __shared__ __align__(128) char smem[];
    const uint32_t sbase = smem_u32(smem);
    float*  Sc = (float*)smem;                    // [128][68] (epilogue only)
    __half* Ph = (__half*)smem;                   // [128][72] (Q staging, aliased)

    const int tid  = threadIdx.x;
    const int warp = tid >> 5;
    const int lane = tid & 31;
    const int g    = lane >> 2;                   // 0..7
    const int jq   = lane & 3;                    // 0..3 (quad index)
    const int n    = blockIdx.x & 63;
    const int h    = (blockIdx.x >> 6) & 15;
    const int b    = blockIdx.x >> 10;
    const size_t base = ((size_t)(b * NHEADS + h)) * SEQ * HD;
    const int kbase = (n - 1) * BS;

    auto load_kv = [&](int jb) {
        const uint32_t koff = sbase + OFF_KV + (jb % NKV) * KVBUF_BYTES;
        const int kblk = kbase + jb * WKB;
#pragma unroll
        for (int i = 0; i < 2; i++) {
            int idx = tid + i * 256;
            int r = idx >> 3, ch = (idx & 7) << 3;
            int kpos = kblk + r;
            bool ok = (kpos >= 0 && kpos < SEQ);
            uint32_t sz = ok ? 16u : 0u;
            size_t off = ok ? (base + (size_t)kpos * HD + ch) : base;
            CP_ASYNC16Z(koff + (r * KVLD + ch) * 2, K + off, sz);
            CP_ASYNC16Z(koff + WKB * KVLD * 2 + (r * KVLD + ch) * 2, V + off, sz);
        }
    };

    load_kv(0); CP_COMMIT();
    load_kv(1); CP_COMMIT();

    // ---- Q staging -> ldmatrix A fragments ----
    {
        const __half* qb = Q + base + (size_t)(n * BS) * HD;
#pragma unroll
        for (int i = 0; i < 4; i++) {
            int idx = tid + i * 256;
            int r = idx >> 3, ch = (idx & 7) << 3;
            *(uint4*)(Ph + r * PLD + ch) = *(const uint4*)(qb + (size_t)r * HD + ch);
        }
    }
    __syncthreads();

    const int sub = lane >> 3, ri = lane & 7;
    uint32_t qa[4][4];
    {
        int row = warp * 16 + ((sub & 1) << 3) + ri;
        int colb = (sub >> 1) << 3;
#pragma unroll
        for (int ks = 0; ks < 4; ks++) {
            uint32_t addr = sbase + (uint32_t)((row * PLD + ks * 16 + colb) * 2);
            LDM_X4(qa[ks][0], qa[ks][1], qa[ks][2], qa[ks][3], addr);
        }
    }

    // ---- mask bounds ----
    auto rowlo = [&](int r) { int lo = r; if (kbase < 0 && -kbase > lo) lo = -kbase; return lo; };
    auto rowhi = [&](int r) { int hi = r + 256; int lim = SEQ - kbase - 1; if (lim < hi) hi = lim; return hi; };
    const int r0 = warp * 16 + g;
    const int klo0 = rowlo(r0),     khi0 = rowhi(r0);
    const int klo1 = rowlo(r0 + 8), khi1 = rowhi(r0 + 8);
    const int klo_w = rowlo(warp * 16), khi_w = rowhi(warp * 16 + 15);

    float of[8][4];
#pragma unroll
    for (int t = 0; t < 8; t++)
#pragma unroll
        for (int e = 0; e < 4; e++) of[t][e] = 0.0f;
    float lsum0 = 0.f, lsum1 = 0.f;

    for (int jb = 0; jb < NJ; jb++) {
        CP_WAIT(1);
        __syncthreads();

        if (jb + 2 < NJ) load_kv(jb + 2);
        CP_COMMIT();

        const uint32_t kvb = sbase + OFF_KV + (uint32_t)((jb % NKV) * KVBUF_BYTES);
        const int cbase = jb * WKB;

        float sacc[8][4];
#pragma unroll
        for (int t = 0; t < 8; t++)
#pragma unroll
            for (int e = 0; e < 4; e++) sacc[t][e] = 0.0f;

        // ---- S = Q @ K^T (skip fully-masked 16-key chunks, warp-uniform) ----
#pragma unroll
        for (int ntp = 0; ntp < 4; ntp++) {
            int ck = cbase + ntp * 16;
            if (ck + 15 < klo_w || ck > khi_w) continue;
            int keyr = ntp * 16 + ((sub >> 1) << 3) + ri;
#pragma unroll
            for (int kc = 0; kc < 4; kc++) {
                uint32_t addr = kvb + (uint32_t)((keyr * KVLD + kc * 16 + ((sub & 1) << 3)) * 2);
                uint32_t k0, k1, k2, k3;
                LDM_X4(k0, k1, k2, k3, addr);
                uint32_t bA[2] = {k0, k1}, bB[2] = {k2, k3};
                mma16816(sacc[2 * ntp],     qa[kc], bA);
                mma16816(sacc[2 * ntp + 1], qa[kc], bB);
            }
        }

        // ---- per 16-key chunk: exp in regs -> P A-frag -> PV mma ----
#pragma unroll
        for (int kc = 0; kc < 4; kc++) {
            int ck = cbase + kc * 16;
            if (ck + 15 < klo_w || ck > khi_w) continue;

            int kk0 = ck + 2 * jq;        // cols of nt=2kc (c0)
            int kk1 = kk0 + 8;            // cols of nt=2kc+1 (c0)
            float p00 = 0.f, p01 = 0.f, p10 = 0.f, p11 = 0.f;   // row r0
            float q00 = 0.f, q01 = 0.f, q10 = 0.f, q11 = 0.f;   // row r0+8
            if (kk0     >= klo0 && kk0     <= khi0) p00 = __expf(sacc[2*kc][0]     * 0.125f);
            if (kk0 + 1 >= klo0 && kk0 + 1 <= khi0) p01 = __expf(sacc[2*kc][1]     * 0.125f);
            if (kk1     >= klo0 && kk1     <= khi0) p10 = __expf(sacc[2*kc+1][0]   * 0.125f);
            if (kk1 + 1 >= klo0 && kk1 + 1 <= khi0) p11 = __expf(sacc[2*kc+1][1]   * 0.125f);
            if (kk0     >= klo1 && kk0     <= khi1) q00 = __expf(sacc[2*kc][2]     * 0.125f);
            if (kk0 + 1 >= klo1 && kk0 + 1 <= khi1) q01 = __expf(sacc[2*kc][3]     * 0.125f);
            if (kk1     >= klo1 && kk1     <= khi1) q10 = __expf(sacc[2*kc+1][2]   * 0.125f);
            if (kk1 + 1 >= klo1 && kk1 + 1 <= khi1) q11 = __expf(sacc[2*kc+1][3]   * 0.125f);
            lsum0 += p00 + p01 + p10 + p11;
            lsum1 += q00 + q01 + q10 + q11;

            uint32_t pa[4];
            pa[0] = packh2(p00, p01);
            pa[1] = packh2(q00, q01);
            pa[2] = packh2(p10, p11);
            pa[3] = packh2(q10, q11);

            int keyr = kc * 16 + ((sub & 1) << 3) + ri;
#pragma unroll
            for (int htp = 0; htp < 4; htp++) {
                uint32_t addr = kvb + (uint32_t)(WKB * KVLD * 2)
                              + (uint32_t)((keyr * KVLD + htp * 16 + ((sub >> 1) << 3)) * 2);
                uint32_t v0, v1, v2, v3;
                LDM_X4T(v0, v1, v2, v3, addr);
                uint32_t bA[2] = {v0, v1}, bB[2] = {v2, v3};
                mma16816(of[2 * htp],     pa, bA);
                mma16816(of[2 * htp + 1], pa, bB);
            }
        }
    }

    // ---- row-sum reduction (quad) + scale in registers ----
    lsum0 += __shfl_xor_sync(0xFFFFFFFF, lsum0, 1);
    lsum0 += __shfl_xor_sync(0xFFFFFFFF, lsum0, 2);
    lsum1 += __shfl_xor_sync(0xFFFFFFFF, lsum1, 1);
    lsum1 += __shfl_xor_sync(0xFFFFFFFF, lsum1, 2);
    const float rinv0 = 1.0f / lsum0;
    const float rinv1 = 1.0f / lsum1;

    // ---- stage scaled O to Sc ----
#pragma unroll
    for (int ht = 0; ht < 8; ht++) {
        float2 va; va.x = of[ht][0] * rinv0; va.y = of[ht][1] * rinv0;
        float2 vb; vb.x = of[ht][2] * rinv1; vb.y = of[ht][3] * rinv1;
        *(float2*)&Sc[r0 * SCLD + 8 * ht + 2 * jq] = va;
        *(float2*)&Sc[(r0 + 8) * SCLD + 8 * ht + 2 * jq] = vb;
    }
    __syncthreads();

    // ---- convert + write half output [B,S,D] ----
#pragma unroll
    for (int i = 0; i < 4; i++) {
        int idx = tid + i * 256;
        int r = idx >> 3, ch = (idx & 7) << 3;
        float4 f0 = *(float4*)&Sc[r * SCLD + ch];
        float4 f1 = *(float4*)&Sc[r * SCLD + ch + 4];
        __half2 a = __floats2half2_rn(f0.x, f0.y);
        __half2 bb2 = __floats2half2_rn(f0.z, f0.w);
        __half2 cc = __floats2half2_rn(f1.x, f1.y);
        __half2 d = __floats2half2_rn(f1.z, f1.w);
        uint4 o;
        o.x = *(uint32_t*)&a; o.y = *(uint32_t*)&bb2;
        o.z = *(uint32_t*)&cc; o.w = *(uint32_t*)&d;
        *(uint4*)&O[((size_t)b * SEQ + (size_t)n * BS + r) * DMODEL + h * HD + ch] = o;
    }
}

// ---------------------------------------------------------------------------
// Launch
// ---------------------------------------------------------------------------
extern "C" void kernel_launch(void* const* d_in, const int* in_sizes, int n_in,
                              void* d_out, int out_size)
{
    const float* x  = (const float*)d_in[0];
    const float* Wq = (const float*)d_in[1];
    const float* bq = (const float*)d_in[2];
    const float* Wk = (const float*)d_in[3];
    const float* bk = (const float*)d_in[4];
    const float* Wv = (const float*)d_in[5];
    const float* bv = (const float*)d_in[6];
    const float* Wo = (const float*)d_in[7];
    const float* bo = (const float*)d_in[8];
    float* out = (float*)d_out;

    __half *xh, *wqkv, *wo, *ah, *qkv;
    cudaGetSymbolAddress((void**)&xh,   g_xh);
    cudaGetSymbolAddress((void**)&wqkv, g_wqkv);
    cudaGetSymbolAddress((void**)&wo,   g_wo);
    cudaGetSymbolAddress((void**)&ah,   g_attnh);
    cudaGetSymbolAddress((void**)&qkv,  g_qkvh);

    cudaFuncSetAttribute(gemm_h_kernel<0>,
                         cudaFuncAttributeMaxDynamicSharedMemorySize, GEMM_SMEM);
    cudaFuncSetAttribute(gemm_h_kernel<1>,
                         cudaFuncAttributeMaxDynamicSharedMemorySize, GEMM_SMEM);
    cudaFuncSetAttribute(attn_kernel,
                         cudaFuncAttributeMaxDynamicSharedMemorySize, ATTN_SMEM);

    convert_all_kernel<<<2048, 256>>>(x, Wq, Wk, Wv, Wo);

    dim3 qgrid(3 * DMODEL / 128, (BATCH * SEQ) / 128);   // (24,128)
    gemm_h_kernel<1><<<qgrid, 128, GEMM_SMEM>>>(xh, wqkv, bq, bk, bv, qkv);

    attn_kernel<<<BATCH * NHEADS * NBLK, 256, ATTN_SMEM>>>(
        qkv, qkv + QKV_SEG, qkv + 2 * QKV_SEG, ah);

    dim3 ogrid(DMODEL / 128, (BATCH * SEQ) / 128);       // (8,128)
    gemm_h_kernel<0><<<ogrid, 128, GEMM_SMEM>>>(ah, wo, bo, bo, bo, out);
}